// round 4
// baseline (speedup 1.0000x reference)
#include <cuda_runtime.h>
#include <cuda_bf16.h>

// QuantumCBOW: B=16384, S=10, DIM=8, TRIL=36.
// R4: 4 lanes per batch element (65536 threads / 2048 warps -> 3.46 warps/SMSP).
//  - lane-split context accumulation + butterfly reduce
//  - per-lane rows of W = C^T sigma C (sigma in smem, C column via smem)
//  - warp-parallel tournament Jacobi with W in shared memory (1 c/s chain per
//    lane per round, rows owned exclusively per lane, width-4 shuffles)

#define QC_DIM  8
#define QC_TRIL 36
#define QC_S    10
#define ELEMS_PER_BLOCK 32
#define QC_STRIDE 76   // smem floats per element (16B-aligned, bank-spread)

__device__ __forceinline__ constexpr int sidx(int i, int j) { return i * (i + 1) / 2 + j; }
__device__ __forceinline__ constexpr int symi(int i, int j) { return (i >= j) ? sidx(i, j) : sidx(j, i); }

// Accumulate wgt * normalized-density(row) into acc[36] (lower-tri storage).
__device__ __forceinline__ void add_density(const float* __restrict__ row, float* acc, float wgt) {
    float L[QC_TRIL];
    const float4* r4 = reinterpret_cast<const float4*>(row);  // 36*4B rows, 16B aligned
#pragma unroll
    for (int v = 0; v < 9; v++) {
        float4 t = r4[v];
        L[4 * v + 0] = t.x; L[4 * v + 1] = t.y;
        L[4 * v + 2] = t.z; L[4 * v + 3] = t.w;
    }
#pragma unroll
    for (int i = 0; i < QC_DIM; i++) {
        const int d = sidx(i, i);
        L[d] = fmaxf(L[d], 1e-4f);
    }
    float tr = 0.f;
#pragma unroll
    for (int i = 0; i < QC_TRIL; i++) tr = fmaf(L[i], L[i], tr);
    const float inv = wgt * __fdividef(1.0f, tr + 1.7e-5f);
#pragma unroll
    for (int i = 0; i < QC_DIM; i++) {
#pragma unroll
        for (int j = 0; j <= i; j++) {
            float s = 0.f;
#pragma unroll
            for (int k = 0; k <= j; k++)
                s = fmaf(L[sidx(i, k)], L[sidx(j, k)], s);
            if (i == j) s += 2e-6f;  // eps + corr
            acc[sidx(i, j)] = fmaf(s, inv, acc[sidx(i, j)]);
        }
    }
}

// Column rotation on one register-resident row, compile-time positions.
#define CROT(R, A, Bq, cc, ss) do {                                            \
    const float _x = R[A], _y = R[Bq];                                         \
    R[A]  = fmaf(cc, _x, -(ss) * _y);                                          \
    R[Bq] = fmaf(ss, _x,  (cc) * _y);                                          \
} while (0)

// One tournament round. (A0,B0)..(A3,B3) are the 4 disjoint pairs (compile-time).
// Lane l owns pair (A_l, B_l): reads/writes exactly rows A_l and B_l of W in smem.
#define ROUND(A0, B0, A1, B1, A2, B2, A3, B3) do {                             \
    const int ra = (l == 0) ? A0 : (l == 1) ? A1 : (l == 2) ? A2 : A3;         \
    const int rb = (l == 0) ? B0 : (l == 1) ? B1 : (l == 2) ? B2 : B3;         \
    const float app = wbase[ra * 9];                                           \
    const float apq = wbase[ra * 8 + rb];                                      \
    const float aqq = wbase[rb * 9];                                           \
    const float dd = aqq - app;                                                \
    const float a2 = 2.0f * apq;                                               \
    const float vv = fmaf(dd, dd, fmaf(a2, a2, 1e-30f));                       \
    const float uu = vv * rsqrtf(vv);                                          \
    const float tt = __fdividef(a2 * copysignf(1.0f, dd), fabsf(dd) + uu);     \
    const float c  = rsqrtf(fmaf(tt, tt, 1.0f));                               \
    const float s  = tt * c;                                                   \
    const float c0 = __shfl_sync(0xffffffffu, c, 0, 4);                        \
    const float s0 = __shfl_sync(0xffffffffu, s, 0, 4);                        \
    const float c1 = __shfl_sync(0xffffffffu, c, 1, 4);                        \
    const float s1 = __shfl_sync(0xffffffffu, s, 1, 4);                        \
    const float c2 = __shfl_sync(0xffffffffu, c, 2, 4);                        \
    const float s2 = __shfl_sync(0xffffffffu, s, 2, 4);                        \
    const float c3 = __shfl_sync(0xffffffffu, c, 3, 4);                        \
    const float s3 = __shfl_sync(0xffffffffu, s, 3, 4);                        \
    float Ra[8], Rb[8];                                                        \
    {                                                                          \
        float4 t0 = *reinterpret_cast<float4*>(wbase + ra * 8);                \
        float4 t1 = *reinterpret_cast<float4*>(wbase + ra * 8 + 4);            \
        float4 t2 = *reinterpret_cast<float4*>(wbase + rb * 8);                \
        float4 t3 = *reinterpret_cast<float4*>(wbase + rb * 8 + 4);            \
        Ra[0]=t0.x; Ra[1]=t0.y; Ra[2]=t0.z; Ra[3]=t0.w;                        \
        Ra[4]=t1.x; Ra[5]=t1.y; Ra[6]=t1.z; Ra[7]=t1.w;                        \
        Rb[0]=t2.x; Rb[1]=t2.y; Rb[2]=t2.z; Rb[3]=t2.w;                        \
        Rb[4]=t3.x; Rb[5]=t3.y; Rb[6]=t3.z; Rb[7]=t3.w;                        \
    }                                                                          \
    CROT(Ra, A0, B0, c0, s0); CROT(Ra, A1, B1, c1, s1);                        \
    CROT(Ra, A2, B2, c2, s2); CROT(Ra, A3, B3, c3, s3);                        \
    CROT(Rb, A0, B0, c0, s0); CROT(Rb, A1, B1, c1, s1);                        \
    CROT(Rb, A2, B2, c2, s2); CROT(Rb, A3, B3, c3, s3);                        \
    float Na[8], Nb[8];                                                        \
    _Pragma("unroll")                                                          \
    for (int k = 0; k < 8; k++) {                                              \
        Na[k] = fmaf(c, Ra[k], -s * Rb[k]);                                    \
        Nb[k] = fmaf(s, Ra[k],  c * Rb[k]);                                    \
    }                                                                          \
    *reinterpret_cast<float4*>(wbase + ra * 8)     = make_float4(Na[0], Na[1], Na[2], Na[3]); \
    *reinterpret_cast<float4*>(wbase + ra * 8 + 4) = make_float4(Na[4], Na[5], Na[6], Na[7]); \
    *reinterpret_cast<float4*>(wbase + rb * 8)     = make_float4(Nb[0], Nb[1], Nb[2], Nb[3]); \
    *reinterpret_cast<float4*>(wbase + rb * 8 + 4) = make_float4(Nb[4], Nb[5], Nb[6], Nb[7]); \
    __syncwarp();                                                              \
} while (0)

__global__ void __launch_bounds__(128, 4)
qcbow_kernel(const int* __restrict__ contexts,
             const int* __restrict__ targets,
             const float* __restrict__ emb,
             float* __restrict__ out,
             int B) {
    __shared__ float sm[ELEMS_PER_BLOCK * QC_STRIDE];

    const int tid = threadIdx.x;
    const int l = tid & 3;                       // lane within 4-lane group
    const int eb = tid >> 2;                     // element within block
    const int elem = blockIdx.x * ELEMS_PER_BLOCK + eb;
    if (elem >= B) return;

    float* const wbase = sm + eb * QC_STRIDE;    // [0..63] W rows / C temp
    float* const smC = wbase;                    // C at [0..35]
    float* const smS = wbase + 36;               // sigma at [36..71]

    // ---- phase 1: lane-split context accumulation (tokens l, l+4, l+8) ----
    const int t2v = (l + 8 < QC_S);              // lanes 0,1 have a 3rd token
    const int tok0 = contexts[elem * QC_S + l];
    const int tok1 = contexts[elem * QC_S + l + 4];
    const int tok2 = contexts[elem * QC_S + (t2v ? (l + 8) : l)];
    const int tgt  = targets[elem];

    float ctx[QC_TRIL];
#pragma unroll
    for (int i = 0; i < QC_TRIL; i++) ctx[i] = 0.f;
    float cnt = 0.f;
    {
        const float m0 = (tok0 != 0) ? 1.0f : 0.0f;
        const float m1 = (tok1 != 0) ? 1.0f : 0.0f;
        const float m2 = (t2v && tok2 != 0) ? 1.0f : 0.0f;
        cnt = m0 + m1 + m2;
        add_density(emb + (long)tok0 * QC_TRIL, ctx, m0);
        add_density(emb + (long)tok1 * QC_TRIL, ctx, m1);
        add_density(emb + (long)tok2 * QC_TRIL, ctx, m2);
    }
    // butterfly reduce over the 4-lane group
#pragma unroll
    for (int i = 0; i < QC_TRIL; i++) ctx[i] += __shfl_xor_sync(0xffffffffu, ctx[i], 1);
    cnt += __shfl_xor_sync(0xffffffffu, cnt, 1);
#pragma unroll
    for (int i = 0; i < QC_TRIL; i++) ctx[i] += __shfl_xor_sync(0xffffffffu, ctx[i], 2);
    cnt += __shfl_xor_sync(0xffffffffu, cnt, 2);
    {
        const float ic = __fdividef(1.0f, cnt);  // cnt==0 -> inf, matches ref 0/0
#pragma unroll
        for (int i = 0; i < QC_TRIL; i++) ctx[i] *= ic;
    }

    // ---- target sigma (redundant per lane; parked in smem, regs freed) ----
    {
        float sig[QC_TRIL];
#pragma unroll
        for (int i = 0; i < QC_TRIL; i++) sig[i] = 0.f;
        add_density(emb + (long)tgt * QC_TRIL, sig, 1.0f);
#pragma unroll
        for (int i = 0; i < 9; i++) smS[l * 9 + i] = sig[l * 9 + i];
    }

    // ---- in-place Cholesky of (ctx + 1e-6 I): ctx becomes C ----
#pragma unroll
    for (int j = 0; j < QC_DIM; j++) {
        float d = ctx[sidx(j, j)] + 1e-6f;
#pragma unroll
        for (int k = 0; k < j; k++) d = fmaf(-ctx[sidx(j, k)], ctx[sidx(j, k)], d);
        d = fmaxf(d, 1e-14f);
        const float icjj = rsqrtf(d);
        ctx[sidx(j, j)] = d * icjj;
#pragma unroll
        for (int i = j + 1; i < QC_DIM; i++) {
            float v = ctx[sidx(i, j)];
#pragma unroll
            for (int k = 0; k < j; k++) v = fmaf(-ctx[sidx(i, k)], ctx[sidx(j, k)], v);
            ctx[sidx(i, j)] = v * icjj;
        }
    }
    // park C in smem (for runtime-column reads)
#pragma unroll
    for (int i = 0; i < 9; i++) smC[l * 9 + i] = ctx[l * 9 + i];
    __syncwarp();

    // ---- phase 3: my two rows of W = C^T sigma C (rows of round-0 pair) ----
    // round-0 pairs: lane0 (0,7), lane1 (6,1), lane2 (5,2), lane3 (4,3)
    const int ra0 = (l == 0) ? 0 : 7 - l;
    const int rb0 = (l == 0) ? 7 : l;
    float va[QC_DIM], vb[QC_DIM], ta[QC_DIM], tb[QC_DIM];
#pragma unroll
    for (int k = 0; k < QC_DIM; k++) {
        va[k] = (k >= ra0) ? smC[k * (k + 1) / 2 + ra0] : 0.f;
        vb[k] = (k >= rb0) ? smC[k * (k + 1) / 2 + rb0] : 0.f;
    }
#pragma unroll
    for (int k = 0; k < QC_DIM; k++) {
        float sa = 0.f, sb = 0.f;
#pragma unroll
        for (int m = 0; m < QC_DIM; m++) {
            const float sv = smS[symi(k, m)];
            sa = fmaf(sv, va[m], sa);
            sb = fmaf(sv, vb[m], sb);
        }
        ta[k] = sa; tb[k] = sb;
    }
    float wa[QC_DIM], wb[QC_DIM];
#pragma unroll
    for (int j = 0; j < QC_DIM; j++) {
        float sa = 0.f, sb = 0.f;
#pragma unroll
        for (int k = j; k < QC_DIM; k++) {       // C[k][j] nonzero for k>=j (regs)
            sa = fmaf(ta[k], ctx[sidx(k, j)], sa);
            sb = fmaf(tb[k], ctx[sidx(k, j)], sb);
        }
        wa[j] = sa; wb[j] = sb;
    }
    __syncwarp();  // all lanes done reading C/sigma before W overwrites them
    *reinterpret_cast<float4*>(wbase + ra0 * 8)     = make_float4(wa[0], wa[1], wa[2], wa[3]);
    *reinterpret_cast<float4*>(wbase + ra0 * 8 + 4) = make_float4(wa[4], wa[5], wa[6], wa[7]);
    *reinterpret_cast<float4*>(wbase + rb0 * 8)     = make_float4(wb[0], wb[1], wb[2], wb[3]);
    *reinterpret_cast<float4*>(wbase + rb0 * 8 + 4) = make_float4(wb[4], wb[5], wb[6], wb[7]);
    __syncwarp();

    // ---- phase 4: warp-parallel tournament Jacobi, 5 sweeps x 7 rounds ----
#pragma unroll 1
    for (int sweep = 0; sweep < 5; sweep++) {
        ROUND(0, 7, 6, 1, 5, 2, 4, 3);
        ROUND(1, 7, 0, 2, 6, 3, 5, 4);
        ROUND(2, 7, 1, 3, 0, 4, 6, 5);
        ROUND(3, 7, 2, 4, 1, 5, 0, 6);
        ROUND(4, 7, 3, 5, 2, 6, 1, 0);
        ROUND(5, 7, 4, 6, 3, 0, 2, 1);
        ROUND(6, 7, 5, 0, 4, 1, 3, 2);
    }

    // ---- f = sum sqrt(|diag| + eps); out = -log(clip(f)) ----
    {
        const float d0 = fabsf(wbase[9 * l]) + 1e-6f;
        const float d1 = fabsf(wbase[9 * l + 36]) + 1e-6f;   // diag l+4
        float p = fmaf(d0, rsqrtf(d0), d1 * rsqrtf(d1));
        p += __shfl_xor_sync(0xffffffffu, p, 1);
        p += __shfl_xor_sync(0xffffffffu, p, 2);
        if (l == 0) {
            float f = fminf(p, 1.0f);
            f = fmaxf(f, 1e-8f);
            out[elem] = -logf(f);
        }
    }
}

extern "C" void kernel_launch(void* const* d_in, const int* in_sizes, int n_in,
                              void* d_out, int out_size) {
    const int*   contexts = (const int*)d_in[0];   // [B, 10] int32
    const int*   targets  = (const int*)d_in[1];   // [B] int32
    const float* emb      = (const float*)d_in[2]; // [V, 36] float32
    float*       out      = (float*)d_out;         // [B] float32
    const int B = in_sizes[1];
    const int blocks = (B + ELEMS_PER_BLOCK - 1) / ELEMS_PER_BLOCK;
    qcbow_kernel<<<blocks, 128>>>(contexts, targets, emb, out, B);
}

// round 5
// speedup vs baseline: 1.1740x; 1.1740x over previous
#include <cuda_runtime.h>
#include <cuda_bf16.h>

// QuantumCBOW: B=16384, S=10, DIM=8, TRIL=36.
// R5: 4 lanes/element (2048 warps, 3.46/SMSP), ZERO smem.
//  F = sum sqrt(eig(C^T sigma C)+eps) = sum sqrt(colnorm^2(A)+eps) after
//  one-sided Jacobi on A = S^T C  (C C^T = ctx+1e-6 I, S S^T = sigma).
//  Lane l owns columns {l, l+4} in registers; pairs via __shfl_xor (m=1,2,3,
//  straight+crossed) + one local round = all 28 pairs/sweep. No row updates,
//  no smem, no column migration.

#define QC_DIM  8
#define QC_TRIL 36
#define QC_S    10
#define ELEMS_PER_BLOCK 32

__device__ __forceinline__ constexpr int sidx(int i, int j) { return i * (i + 1) / 2 + j; }

// Accumulate wgt * normalized-density(row) into acc[36] (lower-tri storage).
__device__ __forceinline__ void add_density(const float* __restrict__ row, float* acc, float wgt) {
    float L[QC_TRIL];
    const float4* r4 = reinterpret_cast<const float4*>(row);  // 36*4B rows, 16B aligned
#pragma unroll
    for (int v = 0; v < 9; v++) {
        float4 t = r4[v];
        L[4 * v + 0] = t.x; L[4 * v + 1] = t.y;
        L[4 * v + 2] = t.z; L[4 * v + 3] = t.w;
    }
#pragma unroll
    for (int i = 0; i < QC_DIM; i++) {
        const int d = sidx(i, i);
        L[d] = fmaxf(L[d], 1e-4f);
    }
    float tr = 0.f;
#pragma unroll
    for (int i = 0; i < QC_TRIL; i++) tr = fmaf(L[i], L[i], tr);
    const float inv = wgt * __fdividef(1.0f, tr + 1.7e-5f);
#pragma unroll
    for (int i = 0; i < QC_DIM; i++) {
#pragma unroll
        for (int j = 0; j <= i; j++) {
            float s = 0.f;
#pragma unroll
            for (int k = 0; k <= j; k++)
                s = fmaf(L[sidx(i, k)], L[sidx(j, k)], s);
            if (i == j) s += 2e-6f;  // eps + corr
            acc[sidx(i, j)] = fmaf(s, inv, acc[sidx(i, j)]);
        }
    }
}

// In-place packed Cholesky of M (+diag_add on the diagonal).
#define CHOL(M, diag_add) do {                                                 \
    _Pragma("unroll")                                                          \
    for (int j = 0; j < QC_DIM; j++) {                                         \
        float d = M[sidx(j, j)] + (diag_add);                                  \
        _Pragma("unroll")                                                      \
        for (int k = 0; k < j; k++) d = fmaf(-M[sidx(j, k)], M[sidx(j, k)], d);\
        d = fmaxf(d, 1e-20f);                                                  \
        const float icjj = rsqrtf(d);                                          \
        M[sidx(j, j)] = d * icjj;                                              \
        _Pragma("unroll")                                                      \
        for (int i = j + 1; i < QC_DIM; i++) {                                 \
            float v = M[sidx(i, j)];                                           \
            _Pragma("unroll")                                                  \
            for (int k = 0; k < j; k++)                                        \
                v = fmaf(-M[sidx(i, k)], M[sidx(j, k)], v);                    \
            M[sidx(i, j)] = v * icjj;                                          \
        }                                                                      \
    }                                                                          \
} while (0)

// Lower-tri element with compile-time zero padding (k, j literals when unrolled).
#define CEL(k, j) (((k) >= (j)) ? ctx[(k) * ((k) + 1) / 2 + (j)] : 0.0f)

// One-sided rotation of own column colx against partner column px.
// Both lanes of a pair run this same formula with locally-seen (nx, pnx);
// the sign flip of dd on the two sides makes the updates consistent.
#define OS_ROT(colx, px, nx, pnx) do {                                         \
    float g = 0.f;                                                             \
    _Pragma("unroll")                                                          \
    for (int k = 0; k < QC_DIM; k++) g = fmaf(colx[k], px[k], g);              \
    const float dd = (pnx) - (nx);                                             \
    const float a2 = 2.0f * g;                                                 \
    const float vv = fmaf(dd, dd, fmaf(a2, a2, 1e-30f));                       \
    const float u  = vv * rsqrtf(vv);                                          \
    const float t  = __fdividef(a2 * copysignf(1.0f, dd), fabsf(dd) + u);      \
    const float c  = rsqrtf(fmaf(t, t, 1.0f));                                 \
    const float s  = t * c;                                                    \
    _Pragma("unroll")                                                          \
    for (int k = 0; k < QC_DIM; k++)                                           \
        colx[k] = fmaf(c, colx[k], -s * px[k]);                                \
    nx = fmaf(-t, g, nx);                                                      \
} while (0)

// Local rotation of the pair (ca, cb) owned by this lane.
#define OS_LOCAL() do {                                                        \
    float g = 0.f;                                                             \
    _Pragma("unroll")                                                          \
    for (int k = 0; k < QC_DIM; k++) g = fmaf(ca[k], cb[k], g);                \
    const float dd = nb - na;                                                  \
    const float a2 = 2.0f * g;                                                 \
    const float vv = fmaf(dd, dd, fmaf(a2, a2, 1e-30f));                       \
    const float u  = vv * rsqrtf(vv);                                          \
    const float t  = __fdividef(a2 * copysignf(1.0f, dd), fabsf(dd) + u);      \
    const float c  = rsqrtf(fmaf(t, t, 1.0f));                                 \
    const float s  = t * c;                                                    \
    _Pragma("unroll")                                                          \
    for (int k = 0; k < QC_DIM; k++) {                                         \
        const float x = ca[k], y = cb[k];                                      \
        ca[k] = fmaf(c, x, -s * y);                                            \
        cb[k] = fmaf(s, x,  c * y);                                            \
    }                                                                          \
    na = fmaf(-t, g, na);                                                      \
    nb = fmaf( t, g, nb);                                                      \
} while (0)

// Cross round: exchange with lane l^m. CROSSED=0: (ca<->p.ca, cb<->p.cb);
// CROSSED=1: (ca<->p.cb, cb<->p.ca). m in {1,2,3} stays inside the 4-lane group.
#define OS_CROSS(m, CROSSED) do {                                              \
    float pa[QC_DIM], pb[QC_DIM];                                              \
    _Pragma("unroll")                                                          \
    for (int k = 0; k < QC_DIM; k++) {                                         \
        pa[k] = __shfl_xor_sync(0xffffffffu, (CROSSED) ? cb[k] : ca[k], (m));  \
        pb[k] = __shfl_xor_sync(0xffffffffu, (CROSSED) ? ca[k] : cb[k], (m));  \
    }                                                                          \
    float pna = __shfl_xor_sync(0xffffffffu, (CROSSED) ? nb : na, (m));        \
    float pnb = __shfl_xor_sync(0xffffffffu, (CROSSED) ? na : nb, (m));        \
    OS_ROT(ca, pa, na, pna);                                                   \
    OS_ROT(cb, pb, nb, pnb);                                                   \
} while (0)

__global__ void __launch_bounds__(128, 4)
qcbow_kernel(const int* __restrict__ contexts,
             const int* __restrict__ targets,
             const float* __restrict__ emb,
             float* __restrict__ out,
             int B) {
    const int tid = threadIdx.x;
    const int l = tid & 3;                       // lane within 4-lane group
    const int eb = tid >> 2;                     // element within block
    const int elem = blockIdx.x * ELEMS_PER_BLOCK + eb;
    if (elem >= B) return;

    // ---- phase 1: lane-split context accumulation (tokens l, l+4, [l+8]) ----
    const int t2v = (l + 8 < QC_S);              // lanes 0,1 have a 3rd token
    const int tok0 = contexts[elem * QC_S + l];
    const int tok1 = contexts[elem * QC_S + l + 4];
    const int tok2 = contexts[elem * QC_S + (t2v ? (l + 8) : l)];
    const int tgt  = targets[elem];

    float ctx[QC_TRIL];
#pragma unroll
    for (int i = 0; i < QC_TRIL; i++) ctx[i] = 0.f;
    float cnt;
    {
        const float m0 = (tok0 != 0) ? 1.0f : 0.0f;
        const float m1 = (tok1 != 0) ? 1.0f : 0.0f;
        const float m2 = (t2v && tok2 != 0) ? 1.0f : 0.0f;
        cnt = m0 + m1 + m2;
        add_density(emb + (long)tok0 * QC_TRIL, ctx, m0);
        add_density(emb + (long)tok1 * QC_TRIL, ctx, m1);
        add_density(emb + (long)tok2 * QC_TRIL, ctx, m2);
    }
    // butterfly reduce over the 4-lane group
#pragma unroll
    for (int i = 0; i < QC_TRIL; i++) ctx[i] += __shfl_xor_sync(0xffffffffu, ctx[i], 1);
    cnt += __shfl_xor_sync(0xffffffffu, cnt, 1);
#pragma unroll
    for (int i = 0; i < QC_TRIL; i++) ctx[i] += __shfl_xor_sync(0xffffffffu, ctx[i], 2);
    cnt += __shfl_xor_sync(0xffffffffu, cnt, 2);
    {
        const float ic = __fdividef(1.0f, cnt);  // cnt==0 -> inf, matches ref 0/0
#pragma unroll
        for (int i = 0; i < QC_TRIL; i++) ctx[i] *= ic;
    }

    // ---- phase 2: sigma (redundant per lane, stays in registers) ----
    float sig[QC_TRIL];
#pragma unroll
    for (int i = 0; i < QC_TRIL; i++) sig[i] = 0.f;
    add_density(emb + (long)tgt * QC_TRIL, sig, 1.0f);

    // ---- Cholesky: ctx -> C with CC^T = ctx+1e-6 I;  sig -> S with SS^T = sigma ----
    CHOL(ctx, 1e-6f);
    CHOL(sig, 0.0f);

    // ---- phase 3: my two columns of A = S^T C  (cols l and l+4) ----
    // Gather C[:,l] and C[:,l+4] with compile-time zero padding + lane selects.
    float Cl[QC_DIM], Cm[QC_DIM];
#pragma unroll
    for (int k = 0; k < QC_DIM; k++) {
        Cl[k] = (l == 0) ? CEL(k, 0) : (l == 1) ? CEL(k, 1) : (l == 2) ? CEL(k, 2) : CEL(k, 3);
        Cm[k] = (l == 0) ? CEL(k, 4) : (l == 1) ? CEL(k, 5) : (l == 2) ? CEL(k, 6) : CEL(k, 7);
    }
    // A[i][j] = sum_{k>=i} S[k][i] * C[k][j]  (zero-padded C handles k<j)
    float ca[QC_DIM], cb[QC_DIM];
#pragma unroll
    for (int i = 0; i < QC_DIM; i++) {
        float sa = 0.f, sb = 0.f;
#pragma unroll
        for (int k = i; k < QC_DIM; k++) {
            const float sv = sig[sidx(k, i)];
            sa = fmaf(sv, Cl[k], sa);
            sb = fmaf(sv, Cm[k], sb);
        }
        ca[i] = sa; cb[i] = sb;
    }

    // ---- phase 4: one-sided Jacobi, 5 sweeps x (1 local + 6 cross) rounds ----
    float na, nb;
#pragma unroll 1
    for (int sweep = 0; sweep < 5; sweep++) {
        // fresh norms each sweep (kills incremental drift)
        na = 0.f; nb = 0.f;
#pragma unroll
        for (int k = 0; k < QC_DIM; k++) {
            na = fmaf(ca[k], ca[k], na);
            nb = fmaf(cb[k], cb[k], nb);
        }
        OS_LOCAL();            // (l, l+4)
        OS_CROSS(1, 0);        // (l, l^1), (l+4, (l^1)+4)
        OS_CROSS(1, 1);        // (l, (l^1)+4), (l+4, l^1)
        OS_CROSS(2, 0);
        OS_CROSS(2, 1);
        OS_CROSS(3, 0);
        OS_CROSS(3, 1);
    }

    // ---- f = sum sqrt(lambda + eps), lambda = squared column norms ----
    {
        const float x0 = na + 1e-6f;
        const float x1 = nb + 1e-6f;
        float p = fmaf(x0, rsqrtf(x0), x1 * rsqrtf(x1));  // sqrt(x) = x*rsqrt(x)
        p += __shfl_xor_sync(0xffffffffu, p, 1);
        p += __shfl_xor_sync(0xffffffffu, p, 2);
        if (l == 0) {
            float f = fminf(p, 1.0f);
            f = fmaxf(f, 1e-8f);
            out[elem] = -logf(f);
        }
    }
}

extern "C" void kernel_launch(void* const* d_in, const int* in_sizes, int n_in,
                              void* d_out, int out_size) {
    const int*   contexts = (const int*)d_in[0];   // [B, 10] int32
    const int*   targets  = (const int*)d_in[1];   // [B] int32
    const float* emb      = (const float*)d_in[2]; // [V, 36] float32
    float*       out      = (float*)d_out;         // [B] float32
    const int B = in_sizes[1];
    const int blocks = (B + ELEMS_PER_BLOCK - 1) / ELEMS_PER_BLOCK;
    qcbow_kernel<<<blocks, 128>>>(contexts, targets, emb, out, B);
}

// round 6
// speedup vs baseline: 1.9421x; 1.6542x over previous
#include <cuda_runtime.h>
#include <cuda_bf16.h>

// QuantumCBOW: B=16384, S=10, DIM=8, TRIL=36.
// R6 = R3 (best chip-wide instruction count: packed symmetric Jacobi,
// 1 thread/element, zero shuffles) + fixes:
//  * 512 blocks x 32 threads -> all 148 SMs busy (R3's 128x128 left 20 idle)
//  * __launch_bounds__(32,8) -> up to 256 regs, no spills
//  * 4 Jacobi sweeps (quadratic-convergence margin vs 1e-3 tolerance)
//  * int2 context-token prefetch for load MLP

#define QC_DIM  8
#define QC_TRIL 36
#define QC_S    10

__device__ __forceinline__ constexpr int sidx(int i, int j) { return i * (i + 1) / 2 + j; }
__device__ __forceinline__ constexpr int symi(int i, int j) { return (i >= j) ? sidx(i, j) : sidx(j, i); }

// Accumulate wgt * normalized-density(row) into acc[36] (lower-tri storage).
__device__ __forceinline__ void add_density(const float* __restrict__ row, float* acc, float wgt) {
    float L[QC_TRIL];
    const float4* r4 = reinterpret_cast<const float4*>(row);  // 36*4B rows, 16B aligned
#pragma unroll
    for (int v = 0; v < 9; v++) {
        float4 t = r4[v];
        L[4 * v + 0] = t.x; L[4 * v + 1] = t.y;
        L[4 * v + 2] = t.z; L[4 * v + 3] = t.w;
    }
#pragma unroll
    for (int i = 0; i < QC_DIM; i++) {
        const int d = sidx(i, i);
        L[d] = fmaxf(L[d], 1e-4f);
    }
    float tr = 0.f;
#pragma unroll
    for (int i = 0; i < QC_TRIL; i++) tr = fmaf(L[i], L[i], tr);
    const float inv = wgt * __fdividef(1.0f, tr + 1.7e-5f);
#pragma unroll
    for (int i = 0; i < QC_DIM; i++) {
#pragma unroll
        for (int j = 0; j <= i; j++) {
            float s = 0.f;
#pragma unroll
            for (int k = 0; k <= j; k++)
                s = fmaf(L[sidx(i, k)], L[sidx(j, k)], s);
            if (i == j) s += 2e-6f;  // eps + corr
            acc[sidx(i, j)] = fmaf(s, inv, acc[sidx(i, j)]);
        }
    }
}

// Packed-symmetric branchless Jacobi rotation on W[36], pair (p,q), p<q.
// Closed-form diagonal: app' = app - t*apq, aqq' = aqq + t*apq, apq' = 0.
#define JROT(p, q) do {                                                        \
    const float apq = W[sidx(q, p)];                                           \
    const float dd  = W[sidx(q, q)] - W[sidx(p, p)];                           \
    const float a2  = 2.0f * apq;                                              \
    const float vv  = fmaf(dd, dd, fmaf(a2, a2, 1e-30f));                      \
    const float u   = vv * rsqrtf(vv);                                         \
    const float t   = __fdividef(a2 * copysignf(1.0f, dd), fabsf(dd) + u);     \
    const float c   = rsqrtf(fmaf(t, t, 1.0f));                                \
    const float s   = t * c;                                                   \
    W[sidx(p, p)] = fmaf(-t, apq, W[sidx(p, p)]);                              \
    W[sidx(q, q)] = fmaf( t, apq, W[sidx(q, q)]);                              \
    W[sidx(q, p)] = 0.0f;                                                      \
    _Pragma("unroll")                                                          \
    for (int k = 0; k < QC_DIM; k++) {                                         \
        if (k != p && k != q) {                                                \
            const float akp = W[symi(k, p)];                                   \
            const float akq = W[symi(k, q)];                                   \
            W[symi(k, p)] = fmaf(c, akp, -s * akq);                            \
            W[symi(k, q)] = fmaf(s, akp,  c * akq);                            \
        }                                                                      \
    }                                                                          \
} while (0)

__global__ void __launch_bounds__(32, 8)
qcbow_kernel(const int* __restrict__ contexts,
             const int* __restrict__ targets,
             const float* __restrict__ emb,
             float* __restrict__ out,
             int B) {
    const int b = blockIdx.x * blockDim.x + threadIdx.x;
    if (b >= B) return;

    // ---- prefetch all token ids (row is 8B-aligned: 10 ints = 5 x int2) ----
    int toks[QC_S];
    {
        const int2* c2 = reinterpret_cast<const int2*>(contexts + b * QC_S);
#pragma unroll
        for (int v = 0; v < 5; v++) {
            const int2 t = c2[v];
            toks[2 * v] = t.x; toks[2 * v + 1] = t.y;
        }
    }
    const int tgt = targets[b];

    // ---- context rho: branchless masked mean of per-token densities ----
    float ctx[QC_TRIL];
#pragma unroll
    for (int i = 0; i < QC_TRIL; i++) ctx[i] = 0.f;
    float cnt = 0.f;
#pragma unroll 2
    for (int t = 0; t < QC_S; t++) {
        const float m = (toks[t] != 0) ? 1.0f : 0.0f;
        cnt += m;
        add_density(emb + (long)toks[t] * QC_TRIL, ctx, m);
    }
    {
        const float ic = __fdividef(1.0f, cnt);  // cnt==0 -> inf, matches ref 0/0
#pragma unroll
        for (int i = 0; i < QC_TRIL; i++) ctx[i] *= ic;
    }

    // ---- in-place Cholesky of (ctx + 1e-6 I): ctx becomes C with C C^T ----
#pragma unroll
    for (int j = 0; j < QC_DIM; j++) {
        float d = ctx[sidx(j, j)] + 1e-6f;
#pragma unroll
        for (int k = 0; k < j; k++) d = fmaf(-ctx[sidx(j, k)], ctx[sidx(j, k)], d);
        d = fmaxf(d, 1e-14f);
        const float icjj = rsqrtf(d);
        ctx[sidx(j, j)] = d * icjj;
#pragma unroll
        for (int i = j + 1; i < QC_DIM; i++) {
            float v = ctx[sidx(i, j)];
#pragma unroll
            for (int k = 0; k < j; k++) v = fmaf(-ctx[sidx(i, k)], ctx[sidx(j, k)], v);
            ctx[sidx(i, j)] = v * icjj;
        }
    }

    // ---- target sigma ----
    float sig[QC_TRIL];
#pragma unroll
    for (int i = 0; i < QC_TRIL; i++) sig[i] = 0.f;
    add_density(emb + (long)tgt * QC_TRIL, sig, 1.0f);

    // ---- W = C^T * sigma * C, packed lower-tri (eig(W) = eig((ctx+eps I) sigma)) ----
    float W[QC_TRIL];
#pragma unroll
    for (int j = 0; j < QC_DIM; j++) {
        float tj[QC_DIM];  // column j of T = sigma * C
#pragma unroll
        for (int i = 0; i < QC_DIM; i++) {
            float s = 0.f;
#pragma unroll
            for (int k = j; k < QC_DIM; k++)      // C[k][j] nonzero for k>=j
                s = fmaf(sig[symi(i, k)], ctx[sidx(k, j)], s);
            tj[i] = s;
        }
#pragma unroll
        for (int i = 0; i <= j; i++) {            // W[i][j], i<=j -> store at sidx(j,i)
            float s = 0.f;
#pragma unroll
            for (int k = i; k < QC_DIM; k++)      // C[k][i] nonzero for k>=i
                s = fmaf(ctx[sidx(k, i)], tj[k], s);
            W[sidx(j, i)] = s;
        }
    }

    // ---- eigenvalues-only packed Jacobi, round-robin: 4 disjoint pairs/round ----
#pragma unroll 1
    for (int sweep = 0; sweep < 4; sweep++) {
        JROT(0, 7); JROT(1, 6); JROT(2, 5); JROT(3, 4);
        JROT(1, 7); JROT(0, 2); JROT(3, 6); JROT(4, 5);
        JROT(2, 7); JROT(1, 3); JROT(0, 4); JROT(5, 6);
        JROT(3, 7); JROT(2, 4); JROT(1, 5); JROT(0, 6);
        JROT(4, 7); JROT(3, 5); JROT(2, 6); JROT(0, 1);
        JROT(5, 7); JROT(4, 6); JROT(0, 3); JROT(1, 2);
        JROT(6, 7); JROT(0, 5); JROT(1, 4); JROT(2, 3);
    }

    // ---- f = sum sqrt(|eig| + eps); out = -log(clip(f)) ----
    float f = 0.f;
#pragma unroll
    for (int i = 0; i < QC_DIM; i++) {
        const float x = fabsf(W[sidx(i, i)]) + 1e-6f;
        f = fmaf(x, rsqrtf(x), f);   // sqrt(x) = x * rsqrt(x), x >= 1e-6
    }
    f = fminf(f, 1.0f);
    f = fmaxf(f, 1e-8f);
    out[b] = -logf(f);
}

extern "C" void kernel_launch(void* const* d_in, const int* in_sizes, int n_in,
                              void* d_out, int out_size) {
    const int*   contexts = (const int*)d_in[0];   // [B, 10] int32
    const int*   targets  = (const int*)d_in[1];   // [B] int32
    const float* emb      = (const float*)d_in[2]; // [V, 36] float32
    float*       out      = (float*)d_out;         // [B] float32
    const int B = in_sizes[1];
    const int threads = 32;                         // 512 blocks -> all 148 SMs busy
    const int blocks = (B + threads - 1) / threads;
    qcbow_kernel<<<blocks, threads>>>(contexts, targets, emb, out, B);
}